// round 11
// baseline (speedup 1.0000x reference)
#include <cuda_runtime.h>
#include <math.h>
#include <stdint.h>

#define K_CODES 1024
#define D_DIM   256
#define N_ROWS  131072

#define FLAG_THRESH  3.0f      // int8 quant: top2-gap err std ~0.48 -> ~6 sigma
#define RESCUE_RPB   8

// ---------------- scratch (device globals; no allocations allowed) ----------
__device__ float        d_cnorm[K_CODES];            // emulated sum(e*e)
__device__ float        d_embedT[K_CODES * D_DIM];   // fp32 codebook, k-major
__device__ float        d_se[K_CODES];               // per-code int8 scale
__device__ uint32_t     d_eBfrag8[64 * 1024];        // preformatted s8 B frags
__device__ unsigned int d_counts[K_CODES];
__device__ float        d_loss_partial[1024];
__device__ int          d_nflag;
__device__ int          d_flaglist[N_ROWS];

__device__ __forceinline__ int q8(float v, float inv) {
    int q = __float2int_rn(v * inv);
    return max(min(q, 127), -127);
}
__device__ __forceinline__ uint32_t q4pack(float4 v, float inv) {
    int a = q8(v.x, inv), b = q8(v.y, inv), c = q8(v.z, inv), d = q8(v.w, inv);
    return (uint32_t)(a & 0xFF) | ((uint32_t)(b & 0xFF) << 8) |
           ((uint32_t)(c & 0xFF) << 16) | ((uint32_t)(d & 0xFF) << 24);
}

// ---------------------------------------------------------------------------
// Prep 1: emulated norms (ascending-d mul-then-add), fp32 transpose, scales
// ---------------------------------------------------------------------------
__global__ void vq_prep(const float* __restrict__ embed) {
    int k = blockIdx.x * blockDim.x + threadIdx.x;  // 0..1023
    float s = 0.0f, amax = 0.0f;
    for (int d = 0; d < D_DIM; ++d) {
        float v = embed[(size_t)d * K_CODES + k];
        s = __fadd_rn(s, __fmul_rn(v, v));
        amax = fmaxf(amax, fabsf(v));
        d_embedT[(size_t)k * D_DIM + d] = v;
    }
    d_cnorm[k]  = s;
    d_se[k]     = fmaxf(amax, 1e-30f) * (1.0f / 127.0f);
    d_counts[k] = 0u;
    if (k == 0) d_nflag = 0;
}

// ---------------------------------------------------------------------------
// Prep 2: s8 B fragments for mma.m16n8k32 (chunk-linear layout)
//   chunk g = kc*8 + dc ; position p = nt*32 + lane (512 per chunk, 2 words)
//   word0: e[db+4t..db+4t+3][code], word1: e[db+16+4t..][code]
//   t = lane&3, code = kc*128 + nt*8 + (lane>>2), db = dc*32
// ---------------------------------------------------------------------------
__global__ void vq_prep_frag8(const float* __restrict__ embed) {
    const int g = blockIdx.x;          // 0..63
    const int kc = g >> 3, dc = g & 7;
    #pragma unroll
    for (int q = 0; q < 2; ++q) {
        int p    = q * 256 + threadIdx.x;   // 0..511
        int nt   = p >> 5;
        int lane = p & 31;
        int t4   = lane & 3;
        int code = kc * 128 + nt * 8 + (lane >> 2);
        int db   = dc * 32 + 4 * t4;
        float inv = 1.0f / d_se[code];
        float4 v0, v1;
        v0.x = embed[(size_t)(db + 0) * K_CODES + code];
        v0.y = embed[(size_t)(db + 1) * K_CODES + code];
        v0.z = embed[(size_t)(db + 2) * K_CODES + code];
        v0.w = embed[(size_t)(db + 3) * K_CODES + code];
        v1.x = embed[(size_t)(db + 16) * K_CODES + code];
        v1.y = embed[(size_t)(db + 17) * K_CODES + code];
        v1.z = embed[(size_t)(db + 18) * K_CODES + code];
        v1.w = embed[(size_t)(db + 19) * K_CODES + code];
        uint32_t* dst = d_eBfrag8 + (size_t)g * 1024 + (size_t)p * 2;
        dst[0] = q4pack(v0, inv);
        dst[1] = q4pack(v1, inv);
    }
}

// ---------------------------------------------------------------------------
// SMEM layout (bytes):
//   [0,4096)       sCn    (1024 f32)
//   [4096,8192)    sSe    (1024 f32)
//   [8192,8704)    sSx    (128 f32)
//   [8704,9216)    sInv   (128 f32)
//   [9216,10240)   sAmax2 (256 f32)
//   [10240,10752)  sIdx   (128 int)
//   [10752,10816)  sRed   (8 f32 + pad)
//   [10816,43584)  fragA8 (8 wid x 8 ks x 32 lanes x 4 regs u32 = 8192 u32)
//   [43584,51776)  fragB8 (2 bufs x 1024 u32)
// 51.8KB/CTA -> 2 CTAs/SM
// ---------------------------------------------------------------------------
#define SM_CN    0
#define SM_SE    4096
#define SM_SX    8192
#define SM_INV   8704
#define SM_AMAX  9216
#define SM_IDX   10240
#define SM_RED   10752
#define SM_A     10816
#define SM_B     43584
#define SMEM_TOTAL 51776
#define BSTRIDE  1024        // u32 per fragB8 buffer

__device__ __forceinline__ void mma_s8(int c[4], uint32_t a0, uint32_t a1,
                                       uint32_t a2, uint32_t a3,
                                       uint32_t b0, uint32_t b1) {
    asm volatile(
        "mma.sync.aligned.m16n8k32.row.col.s32.s8.s8.s32 "
        "{%0,%1,%2,%3}, {%4,%5,%6,%7}, {%8,%9}, {%0,%1,%2,%3};"
        : "+r"(c[0]), "+r"(c[1]), "+r"(c[2]), "+r"(c[3])
        : "r"(a0), "r"(a1), "r"(a2), "r"(a3), "r"(b0), "r"(b1));
}

__device__ __forceinline__ void top2_upd(float& v1, float& v2, int& i1,
                                         float d, int code) {
    if (d < v1)      { v2 = v1; v1 = d; i1 = code; }
    else if (d < v2) { v2 = d; }
}

__global__ void __launch_bounds__(256, 2)
vq_main_mma(const float* __restrict__ inputs, float* __restrict__ out) {
    extern __shared__ char smem[];
    float*    sCn    = (float*)(smem + SM_CN);
    float*    sSe    = (float*)(smem + SM_SE);
    float*    sSx    = (float*)(smem + SM_SX);
    float*    sInv   = (float*)(smem + SM_INV);
    float*    sAmax2 = (float*)(smem + SM_AMAX);
    int*      sIdx   = (int*)(smem + SM_IDX);
    float*    sRed   = (float*)(smem + SM_RED);
    uint32_t* fragA8 = (uint32_t*)(smem + SM_A);
    uint32_t* fragB8 = (uint32_t*)(smem + SM_B);

    const int t    = threadIdx.x;
    const int wid  = t >> 5;
    const int lane = t & 31;
    const int row0 = blockIdx.x * 128;

    for (int i = t; i < K_CODES; i += 256) {
        sCn[i] = d_cnorm[i];
        sSe[i] = d_se[i];
    }

    const float4* inp4 = (const float4*)(inputs + (size_t)row0 * D_DIM);

    // ---- Pass 1: per-row amax (thread = row-half) ----
    {
        int r = t & 127, h = t >> 7;
        float am = 0.0f;
        #pragma unroll 8
        for (int i = 0; i < 32; ++i) {
            float4 v = inp4[r * 64 + h * 32 + i];
            am = fmaxf(am, fmaxf(fmaxf(fabsf(v.x), fabsf(v.y)),
                                 fmaxf(fabsf(v.z), fabsf(v.w))));
        }
        sAmax2[t] = am;
    }
    __syncthreads();
    if (t < 128) {
        float a = fmaxf(fmaxf(sAmax2[t], sAmax2[t + 128]), 1e-30f);
        sSx[t]  = a * (1.0f / 127.0f);
        sInv[t] = 127.0f / a;
    }
    __syncthreads();

    // ---- Pass 2: quantize A into frags (thread = consumer lane) ----
    {
        int rA = wid * 16 + (lane >> 2);
        float invA = sInv[rA], invB = sInv[rA + 8];
        #pragma unroll
        for (int ks = 0; ks < 8; ++ks) {
            uint32_t w[4];
            #pragma unroll
            for (int reg = 0; reg < 4; ++reg) {
                int row = rA + ((reg & 1) << 3);
                int d0  = ks * 32 + ((reg & 2) << 3) + ((lane & 3) << 2);
                float4 v = inp4[row * 64 + (d0 >> 2)];
                w[reg] = q4pack(v, (reg & 1) ? invB : invA);
            }
            *(uint4*)(fragA8 + ((size_t)(wid * 8 + ks) * 32 + lane) * 4) =
                make_uint4(w[0], w[1], w[2], w[3]);
        }
    }

    // ---- Prefetch + stage B chunk g=0 ----
    uint4 pv;
    {
        pv = ((const uint4*)d_eBfrag8)[t];
        ((uint4*)fragB8)[t] = pv;
    }
    __syncthreads();

    int acc[16][4];
    #pragma unroll
    for (int nt = 0; nt < 16; ++nt)
        #pragma unroll
        for (int r = 0; r < 4; ++r) acc[nt][r] = 0;

    float v1a = 3.4e38f, v2a = 3.4e38f; int i1a = 0;   // row wid*16 + lane/4
    float v1b = 3.4e38f, v2b = 3.4e38f; int i1b = 0;   // +8
    const float sa2 = 2.0f * sSx[wid * 16 + (lane >> 2)];
    const float sb2 = 2.0f * sSx[wid * 16 + (lane >> 2) + 8];

    const uint32_t* fA = fragA8 + (size_t)(wid * 8) * 128 + lane * 4;

    for (int g = 0; g < 64; ++g) {          // g = kc*8 + dc
        if (g < 63)
            pv = ((const uint4*)(d_eBfrag8 + (size_t)(g + 1) * 1024))[t];

        // compute chunk g: one k32-step x 16 n-tiles
        {
            const uint32_t* fB = fragB8 + (g & 1) * BSTRIDE + lane * 2;
            uint4 a = *(const uint4*)(fA + (g & 7) * 128);
            #pragma unroll
            for (int nt = 0; nt < 16; ++nt) {
                uint2 b = *(const uint2*)(fB + nt * 64);
                mma_s8(acc[nt], a.x, a.y, a.z, a.w, b.x, b.y);
            }
        }

        // epilogue at end of each kc (8 chunks)
        if ((g & 7) == 7) {
            int kc = g >> 3;
            #pragma unroll
            for (int nt = 0; nt < 16; ++nt) {
                int code = kc * 128 + nt * 8 + (lane & 3) * 2;
                float2 se = *(const float2*)&sSe[code];
                float c0 = sCn[code]     - sa2 * se.x * (float)acc[nt][0];
                float c1 = sCn[code + 1] - sa2 * se.y * (float)acc[nt][1];
                float c2 = sCn[code]     - sb2 * se.x * (float)acc[nt][2];
                float c3 = sCn[code + 1] - sb2 * se.y * (float)acc[nt][3];
                top2_upd(v1a, v2a, i1a, c0, code);
                top2_upd(v1a, v2a, i1a, c1, code + 1);
                top2_upd(v1b, v2b, i1b, c2, code);
                top2_upd(v1b, v2b, i1b, c3, code + 1);
                acc[nt][0] = acc[nt][1] = acc[nt][2] = acc[nt][3] = 0;
            }
        }

        if (g < 63)
            ((uint4*)(fragB8 + ((g + 1) & 1) * BSTRIDE))[t] = pv;
        __syncthreads();
    }

    // ---- merge top-2 across the 4 lanes sharing each row ----
    #pragma unroll
    for (int off = 1; off < 4; off <<= 1) {
        float w1 = __shfl_down_sync(0xffffffffu, v1a, off, 4);
        int   wi = __shfl_down_sync(0xffffffffu, i1a, off, 4);
        float w2 = __shfl_down_sync(0xffffffffu, v2a, off, 4);
        if (w1 < v1a || (w1 == v1a && wi < i1a)) {
            v2a = fminf(v1a, w2); v1a = w1; i1a = wi;
        } else v2a = fminf(v2a, w1);
        w1 = __shfl_down_sync(0xffffffffu, v1b, off, 4);
        wi = __shfl_down_sync(0xffffffffu, i1b, off, 4);
        w2 = __shfl_down_sync(0xffffffffu, v2b, off, 4);
        if (w1 < v1b || (w1 == v1b && wi < i1b)) {
            v2b = fminf(v1b, w2); v1b = w1; i1b = wi;
        } else v2b = fminf(v2b, w1);
    }

    const size_t ND = (size_t)N_ROWS * D_DIM;
    if ((lane & 3) == 0) {
        int rA = wid * 16 + (lane >> 2);
        int rB = rA + 8;
        sIdx[rA] = i1a;
        sIdx[rB] = i1b;
        if (v2a - v1a < FLAG_THRESH) {
            int pos = atomicAdd(&d_nflag, 1);
            d_flaglist[pos] = row0 + rA;
        }
        if (v2b - v1b < FLAG_THRESH) {
            int pos = atomicAdd(&d_nflag, 1);
            d_flaglist[pos] = row0 + rB;
        }
        atomicAdd(&d_counts[i1a], 1u);
        atomicAdd(&d_counts[i1b], 1u);
        out[ND + 2 + (size_t)(row0 + rA)] = (float)i1a;
        out[ND + 2 + (size_t)(row0 + rB)] = (float)i1b;
    }
    __syncthreads();

    // ---- quantize (= q exactly) + loss partials ----
    float lsum = 0.0f;
    float4*       out4 = (float4*)(out + (size_t)row0 * D_DIM);
    const float4* eT4  = (const float4*)d_embedT;
    #pragma unroll 4
    for (int it = 0; it < 32; ++it) {
        int l  = it * 256 + t;
        int r  = l >> 6;
        int d4 = l & 63;
        float4 x = inp4[r * 64 + d4];
        int    k = sIdx[r];
        float4 q = eT4[(size_t)k * 64 + d4];
        float dx = q.x - x.x, dy = q.y - x.y, dz = q.z - x.z, dw = q.w - x.w;
        lsum += dx * dx + dy * dy + dz * dz + dw * dw;
        out4[r * 64 + d4] = q;
    }
    #pragma unroll
    for (int off = 16; off; off >>= 1)
        lsum += __shfl_down_sync(0xffffffffu, lsum, off);
    if ((t & 31) == 0) sRed[t >> 5] = lsum;
    __syncthreads();
    if (t == 0) {
        float s = 0.0f;
        #pragma unroll
        for (int w = 0; w < 8; ++w) s += sRed[w];
        d_loss_partial[blockIdx.x] = s;
    }
}

// ---------------------------------------------------------------------------
// Rescue: re-decide flagged rows with reference-emulated fp32 arithmetic
// ---------------------------------------------------------------------------
__global__ void __launch_bounds__(256)
vq_fix(const float* __restrict__ inputs, float* __restrict__ out) {
    __shared__ float sx[RESCUE_RPB][D_DIM];
    __shared__ float sdist[RESCUE_RPB][K_CODES];
    __shared__ float ssx2[RESCUE_RPB];
    __shared__ int   srow[RESCUE_RPB];
    __shared__ int   sbest[RESCUE_RPB];
    const int t = threadIdx.x;
    const size_t ND = (size_t)N_ROWS * D_DIM;

    const int nf = d_nflag;
    for (int base = blockIdx.x * RESCUE_RPB; base < nf;
         base += gridDim.x * RESCUE_RPB) {
        const int cnt = min(RESCUE_RPB, nf - base);
        __syncthreads();
        if (t < cnt) srow[t] = d_flaglist[base + t];
        __syncthreads();
        for (int r = 0; r < cnt; ++r)
            sx[r][t] = inputs[(size_t)srow[r] * D_DIM + t];
        __syncthreads();
        if (t < cnt) {
            float s = 0.0f;
            for (int d = 0; d < D_DIM; ++d)
                s = __fadd_rn(s, __fmul_rn(sx[t][d], sx[t][d]));
            ssx2[t] = s;
        }
        __syncthreads();

        #pragma unroll
        for (int c = 0; c < 4; ++c) {
            const int k = c * 256 + t;
            const float* e = d_embedT + (size_t)k * D_DIM;
            float acc[RESCUE_RPB];
            #pragma unroll
            for (int r = 0; r < RESCUE_RPB; ++r) acc[r] = 0.0f;
            for (int d = 0; d < D_DIM; ++d) {
                float ev = e[d];
                #pragma unroll
                for (int r = 0; r < RESCUE_RPB; ++r)
                    acc[r] = __fmaf_rn(sx[r][d], ev, acc[r]);
            }
            #pragma unroll
            for (int r = 0; r < RESCUE_RPB; ++r) {
                float twod = __fadd_rn(acc[r], acc[r]);
                float t1   = __fsub_rn(ssx2[r], twod);
                sdist[r][k] = __fadd_rn(t1, d_cnorm[k]);
            }
        }
        __syncthreads();

        if (t < cnt) {
            float best = 3.4e38f; int bk = 0;
            for (int k = 0; k < K_CODES; ++k) {
                float v = sdist[t][k];
                if (v < best) { best = v; bk = k; }
            }
            sbest[t] = bk;
            int oldk = (int)out[ND + 2 + (size_t)srow[t]];
            if (oldk != bk) {
                atomicAdd(&d_counts[bk], 1u);
                atomicAdd(&d_counts[oldk], 0xFFFFFFFFu);
                out[ND + 2 + (size_t)srow[t]] = (float)bk;
            }
        }
        __syncthreads();
        for (int r = 0; r < cnt; ++r)
            out[(size_t)srow[r] * D_DIM + t] =
                d_embedT[(size_t)sbest[r] * D_DIM + t];
    }
}

// ---------------------------------------------------------------------------
// Finalize: loss mean + perplexity
// ---------------------------------------------------------------------------
__global__ void vq_finalize(float* __restrict__ out) {
    __shared__ float sl[1024];
    __shared__ float se[1024];
    int t = threadIdx.x;
    sl[t] = d_loss_partial[t];
    float avg = (float)d_counts[t] * (1.0f / (float)N_ROWS);
    se[t] = avg * logf(avg + 1e-10f);
    __syncthreads();
    for (int s = 512; s; s >>= 1) {
        if (t < s) { sl[t] += sl[t + s]; se[t] += se[t + s]; }
        __syncthreads();
    }
    if (t == 0) {
        const size_t ND = (size_t)N_ROWS * D_DIM;
        out[ND]     = sl[0] / ((float)N_ROWS * (float)D_DIM);
        out[ND + 1] = expf(-se[0]);
    }
}

// ---------------------------------------------------------------------------
extern "C" void kernel_launch(void* const* d_in, const int* in_sizes, int n_in,
                              void* d_out, int out_size) {
    const float* inputs = (const float*)d_in[0];  // [131072, 256]
    const float* embed  = (const float*)d_in[1];  // [256, 1024]
    float* out = (float*)d_out;

    cudaFuncSetAttribute(vq_main_mma,
                         cudaFuncAttributeMaxDynamicSharedMemorySize,
                         SMEM_TOTAL);

    vq_prep<<<8, 128>>>(embed);
    vq_prep_frag8<<<64, 256>>>(embed);
    vq_main_mma<<<N_ROWS / 128, 256, SMEM_TOTAL>>>(inputs, out);
    vq_fix<<<256, 256>>>(inputs, out);
    vq_finalize<<<1, 1024>>>(out);
}

// round 12
// speedup vs baseline: 1.4566x; 1.4566x over previous
#include <cuda_runtime.h>
#include <cuda_fp16.h>
#include <math.h>
#include <stdint.h>

#define K_CODES 1024
#define D_DIM   256
#define N_ROWS  131072

#define FLAG_THRESH  2.0f      // f16-accum top2-gap err std ~0.2-0.4 -> >=5 sigma
#define RESCUE_RPB   8

// ---------------- scratch (device globals; no allocations allowed) ----------
__device__ float        d_cnorm[K_CODES];            // emulated sum(e*e)
__device__ float        d_embedT[K_CODES * D_DIM];   // fp32 codebook, k-major
__device__ uint32_t     d_eBfrag[64 * 2048];         // preformatted f16 B frags
__device__ unsigned int d_counts[K_CODES];
__device__ float        d_loss_partial[1024];
__device__ int          d_nflag;
__device__ int          d_flaglist[N_ROWS];

__device__ __forceinline__ uint32_t pack_h2(float a, float b) {
    __half2 h = __floats2half2_rn(a, b);
    return *(uint32_t*)&h;
}

// ---------------------------------------------------------------------------
// Prep 1: emulated codebook norms (ascending-d, mul-then-add), fp32 transpose
// ---------------------------------------------------------------------------
__global__ void vq_prep(const float* __restrict__ embed) {
    int k = blockIdx.x * blockDim.x + threadIdx.x;  // 0..1023
    float s = 0.0f;
    for (int d = 0; d < D_DIM; ++d) {
        float v = embed[(size_t)d * K_CODES + k];
        s = __fadd_rn(s, __fmul_rn(v, v));
        d_embedT[(size_t)k * D_DIM + d] = v;
    }
    d_cnorm[k]  = s;
    d_counts[k] = 0u;
    if (k == 0) d_nflag = 0;
}

// ---------------------------------------------------------------------------
// Prep 2: build f16 B fragments for mma.m16n8k16 (chunk-linear layout)
//   chunk g = kc*8 + dc ; entry e = ks*512 + nt*32 + lane, 2 words
// ---------------------------------------------------------------------------
__global__ void vq_prep_frag(const float* __restrict__ embed) {
    const int g = blockIdx.x;          // 0..63
    const int kc = g >> 3, dc = g & 7;
    #pragma unroll
    for (int q = 0; q < 4; ++q) {
        int e    = q * 256 + threadIdx.x;   // 0..1023
        int ks   = e >> 9;
        int nt   = (e >> 5) & 15;
        int lane = e & 31;
        int t4   = lane & 3;
        int gq   = lane >> 2;
        int code = kc * 128 + nt * 8 + gq;
        int db   = dc * 32 + ks * 16;
        float e0 = embed[(size_t)(db + 2*t4)     * K_CODES + code];
        float e1 = embed[(size_t)(db + 2*t4 + 1) * K_CODES + code];
        float e2 = embed[(size_t)(db + 2*t4 + 8) * K_CODES + code];
        float e3 = embed[(size_t)(db + 2*t4 + 9) * K_CODES + code];
        uint32_t* dst = d_eBfrag + ((size_t)g * 2048) + (size_t)e * 2;
        dst[0] = pack_h2(e0, e1);
        dst[1] = pack_h2(e2, e3);
    }
}

// ---------------------------------------------------------------------------
// SMEM layout (bytes):
//   [0,4096)       sCn   (1024 f32)
//   [4096,4608)    sIdx  (128 int)
//   [4608,4640)    sRed  (8 f32)
//   [4640,70176)   fragA (8 mt x 16 kstep16 x 32 lanes x 4 regs, f16x2)
//   [70176,86560)  fragB (2 bufs x 2048 u32)
// 86.5KB/CTA -> 2 CTAs/SM
// ---------------------------------------------------------------------------
#define SM_CN   0
#define SM_IDX  4096
#define SM_RED  4608
#define SM_A    4640
#define SM_B    70176
#define SMEM_TOTAL 86560
#define BSTRIDE 2048        // u32 per fragB buffer

// f16-accumulator mma: C fragment = 2 regs of packed half2
//   c[0] = (row grp,  code 2tig | 2tig+1), c[1] = (row grp+8, same codes)
__device__ __forceinline__ void mma_f16(uint32_t c[2], uint32_t a0, uint32_t a1,
                                        uint32_t a2, uint32_t a3,
                                        uint32_t b0, uint32_t b1) {
    asm volatile(
        "mma.sync.aligned.m16n8k16.row.col.f16.f16.f16.f16 "
        "{%0,%1}, {%2,%3,%4,%5}, {%6,%7}, {%0,%1};"
        : "+r"(c[0]), "+r"(c[1])
        : "r"(a0), "r"(a1), "r"(a2), "r"(a3), "r"(b0), "r"(b1));
}

__device__ __forceinline__ void top2_upd(float& v1, float& v2, int& i1,
                                         float d, int code) {
    if (d < v1)      { v2 = v1; v1 = d; i1 = code; }
    else if (d < v2) { v2 = d; }
}

__global__ void __launch_bounds__(256, 2)
vq_main_mma(const float* __restrict__ inputs, float* __restrict__ out) {
    extern __shared__ char smem[];
    float*    sCn   = (float*)(smem + SM_CN);
    int*      sIdx  = (int*)(smem + SM_IDX);
    float*    sRed  = (float*)(smem + SM_RED);
    uint32_t* fragA = (uint32_t*)(smem + SM_A);
    uint32_t* fragB = (uint32_t*)(smem + SM_B);

    const int t    = threadIdx.x;
    const int wid  = t >> 5;
    const int lane = t & 31;
    const int row0 = blockIdx.x * 128;

    for (int i = t; i < K_CODES; i += 256) sCn[i] = d_cnorm[i];

    // ---- Stage A (128 rows x 256 d) -> f16 fragment-major smem ----
    {
        const float4* in4 = (const float4*)(inputs + (size_t)row0 * D_DIM);
        #pragma unroll
        for (int i = 0; i < 32; ++i) {
            int l   = i * 256 + t;           // 0..8191
            int row = l >> 6;
            int d4  = l & 63;
            float4 v = in4[row * 64 + d4];
            int d   = d4 * 4;
            int mt  = row >> 4, r16 = row & 15;
            int ks16 = d >> 4;               // k16 step 0..15
            int o    = d & 15;
            int reg  = ((o & 8) ? 2 : 0) + ((r16 >= 8) ? 1 : 0);
            int t0   = (o & 7) >> 1;         // thread-in-group for (v.x,v.y)
            uint32_t* p = fragA + ((mt * 16 + ks16) * 32 + (r16 & 7) * 4 + t0) * 4 + reg;
            p[0] = pack_h2(v.x, v.y);
            p[4] = pack_h2(v.z, v.w);        // t0+1 -> +4 u32
        }
    }

    // ---- Prefetch + stage B chunk g=0 (pure copy, conflict-free) ----
    uint4 pv0, pv1;
    {
        const uint4* src = (const uint4*)d_eBfrag;
        pv0 = src[t];
        pv1 = src[t + 256];
        uint4* dst = (uint4*)fragB;
        dst[t]       = pv0;
        dst[t + 256] = pv1;
    }
    __syncthreads();

    uint32_t acc[16][2];
    #pragma unroll
    for (int nt = 0; nt < 16; ++nt) { acc[nt][0] = 0u; acc[nt][1] = 0u; }

    float v1a = 3.4e38f, v2a = 3.4e38f; int i1a = 0;   // row wid*16 + lane/4
    float v1b = 3.4e38f, v2b = 3.4e38f; int i1b = 0;   // +8

    const uint32_t* fA = fragA + wid * 2048 + lane * 4;

    for (int g = 0; g < 64; ++g) {          // g = kc*8 + dc
        // prefetch next B chunk (linear copy from preformatted gmem)
        if (g < 63) {
            const uint4* src = (const uint4*)(d_eBfrag + (size_t)(g + 1) * 2048);
            pv0 = src[t];
            pv1 = src[t + 256];
        }

        // compute chunk g: 2 k16-steps x 16 n-tiles
        {
            const uint32_t* fB = fragB + (g & 1) * BSTRIDE + lane * 2;
            #pragma unroll
            for (int ks = 0; ks < 2; ++ks) {
                int ks16 = (g & 7) * 2 + ks;
                uint4 a = *(const uint4*)(fA + ks16 * 128);
                #pragma unroll
                for (int nt = 0; nt < 16; ++nt) {
                    uint2 b = *(const uint2*)(fB + (ks * 16 + nt) * 64);
                    mma_f16(acc[nt], a.x, a.y, a.z, a.w, b.x, b.y);
                }
            }
        }

        // epilogue at end of each kc (8 chunks)
        if ((g & 7) == 7) {
            int kc = g >> 3;
            #pragma unroll
            for (int nt = 0; nt < 16; ++nt) {
                int code = kc * 128 + nt * 8 + (lane & 3) * 2;
                __half2 hA = *(__half2*)&acc[nt][0];
                __half2 hB = *(__half2*)&acc[nt][1];
                float c0 = sCn[code]     - 2.0f * __low2float(hA);
                float c1 = sCn[code + 1] - 2.0f * __high2float(hA);
                float c2 = sCn[code]     - 2.0f * __low2float(hB);
                float c3 = sCn[code + 1] - 2.0f * __high2float(hB);
                top2_upd(v1a, v2a, i1a, c0, code);
                top2_upd(v1a, v2a, i1a, c1, code + 1);
                top2_upd(v1b, v2b, i1b, c2, code);
                top2_upd(v1b, v2b, i1b, c3, code + 1);
                acc[nt][0] = 0u; acc[nt][1] = 0u;
            }
        }

        // store next B chunk into the other buffer
        if (g < 63) {
            uint4* dst = (uint4*)(fragB + ((g + 1) & 1) * BSTRIDE);
            dst[t]       = pv0;
            dst[t + 256] = pv1;
        }
        __syncthreads();
    }

    // ---- merge top-2 across the 4 lanes sharing each row ----
    #pragma unroll
    for (int off = 1; off < 4; off <<= 1) {
        float w1 = __shfl_down_sync(0xffffffffu, v1a, off, 4);
        int   wi = __shfl_down_sync(0xffffffffu, i1a, off, 4);
        float w2 = __shfl_down_sync(0xffffffffu, v2a, off, 4);
        if (w1 < v1a || (w1 == v1a && wi < i1a)) {
            v2a = fminf(v1a, w2); v1a = w1; i1a = wi;
        } else v2a = fminf(v2a, w1);
        w1 = __shfl_down_sync(0xffffffffu, v1b, off, 4);
        wi = __shfl_down_sync(0xffffffffu, i1b, off, 4);
        w2 = __shfl_down_sync(0xffffffffu, v2b, off, 4);
        if (w1 < v1b || (w1 == v1b && wi < i1b)) {
            v2b = fminf(v1b, w2); v1b = w1; i1b = wi;
        } else v2b = fminf(v2b, w1);
    }

    const size_t ND = (size_t)N_ROWS * D_DIM;
    if ((lane & 3) == 0) {
        int rA = wid * 16 + (lane >> 2);
        int rB = rA + 8;
        sIdx[rA] = i1a;
        sIdx[rB] = i1b;
        if (v2a - v1a < FLAG_THRESH) {
            int pos = atomicAdd(&d_nflag, 1);
            d_flaglist[pos] = row0 + rA;
        }
        if (v2b - v1b < FLAG_THRESH) {
            int pos = atomicAdd(&d_nflag, 1);
            d_flaglist[pos] = row0 + rB;
        }
        atomicAdd(&d_counts[i1a], 1u);
        atomicAdd(&d_counts[i1b], 1u);
        out[ND + 2 + (size_t)(row0 + rA)] = (float)i1a;
        out[ND + 2 + (size_t)(row0 + rB)] = (float)i1b;
    }
    __syncthreads();

    // ---- quantize (= q exactly) + loss partials ----
    float lsum = 0.0f;
    const float4* inp4 = (const float4*)(inputs + (size_t)row0 * D_DIM);
    float4*       out4 = (float4*)(out + (size_t)row0 * D_DIM);
    const float4* eT4  = (const float4*)d_embedT;
    #pragma unroll 4
    for (int it = 0; it < 32; ++it) {
        int l  = it * 256 + t;
        int r  = l >> 6;
        int d4 = l & 63;
        float4 x = inp4[r * 64 + d4];
        int    k = sIdx[r];
        float4 q = eT4[(size_t)k * 64 + d4];
        float dx = q.x - x.x, dy = q.y - x.y, dz = q.z - x.z, dw = q.w - x.w;
        lsum += dx * dx + dy * dy + dz * dz + dw * dw;
        out4[r * 64 + d4] = q;
    }
    #pragma unroll
    for (int off = 16; off; off >>= 1)
        lsum += __shfl_down_sync(0xffffffffu, lsum, off);
    if ((t & 31) == 0) sRed[t >> 5] = lsum;
    __syncthreads();
    if (t == 0) {
        float s = 0.0f;
        #pragma unroll
        for (int w = 0; w < 8; ++w) s += sRed[w];
        d_loss_partial[blockIdx.x] = s;
    }
}

// ---------------------------------------------------------------------------
// Rescue: re-decide flagged rows with reference-emulated fp32 arithmetic
// ---------------------------------------------------------------------------
__global__ void __launch_bounds__(256)
vq_fix(const float* __restrict__ inputs, float* __restrict__ out) {
    __shared__ float sx[RESCUE_RPB][D_DIM];
    __shared__ float sdist[RESCUE_RPB][K_CODES];
    __shared__ float ssx2[RESCUE_RPB];
    __shared__ int   srow[RESCUE_RPB];
    __shared__ int   sbest[RESCUE_RPB];
    const int t = threadIdx.x;
    const size_t ND = (size_t)N_ROWS * D_DIM;

    const int nf = d_nflag;
    for (int base = blockIdx.x * RESCUE_RPB; base < nf;
         base += gridDim.x * RESCUE_RPB) {
        const int cnt = min(RESCUE_RPB, nf - base);
        __syncthreads();
        if (t < cnt) srow[t] = d_flaglist[base + t];
        __syncthreads();
        for (int r = 0; r < cnt; ++r)
            sx[r][t] = inputs[(size_t)srow[r] * D_DIM + t];
        __syncthreads();
        if (t < cnt) {
            float s = 0.0f;
            for (int d = 0; d < D_DIM; ++d)
                s = __fadd_rn(s, __fmul_rn(sx[t][d], sx[t][d]));
            ssx2[t] = s;
        }
        __syncthreads();

        #pragma unroll
        for (int c = 0; c < 4; ++c) {
            const int k = c * 256 + t;
            const float* e = d_embedT + (size_t)k * D_DIM;
            float acc[RESCUE_RPB];
            #pragma unroll
            for (int r = 0; r < RESCUE_RPB; ++r) acc[r] = 0.0f;
            for (int d = 0; d < D_DIM; ++d) {
                float ev = e[d];
                #pragma unroll
                for (int r = 0; r < RESCUE_RPB; ++r)
                    acc[r] = __fmaf_rn(sx[r][d], ev, acc[r]);
            }
            #pragma unroll
            for (int r = 0; r < RESCUE_RPB; ++r) {
                float twod = __fadd_rn(acc[r], acc[r]);
                float t1   = __fsub_rn(ssx2[r], twod);
                sdist[r][k] = __fadd_rn(t1, d_cnorm[k]);
            }
        }
        __syncthreads();

        if (t < cnt) {
            float best = 3.4e38f; int bk = 0;
            for (int k = 0; k < K_CODES; ++k) {
                float v = sdist[t][k];
                if (v < best) { best = v; bk = k; }
            }
            sbest[t] = bk;
            int oldk = (int)out[ND + 2 + (size_t)srow[t]];
            if (oldk != bk) {
                atomicAdd(&d_counts[bk], 1u);
                atomicAdd(&d_counts[oldk], 0xFFFFFFFFu);
                out[ND + 2 + (size_t)srow[t]] = (float)bk;
            }
        }
        __syncthreads();
        for (int r = 0; r < cnt; ++r)
            out[(size_t)srow[r] * D_DIM + t] =
                d_embedT[(size_t)sbest[r] * D_DIM + t];
    }
}

// ---------------------------------------------------------------------------
// Finalize: loss mean + perplexity
// ---------------------------------------------------------------------------
__global__ void vq_finalize(float* __restrict__ out) {
    __shared__ float sl[1024];
    __shared__ float se[1024];
    int t = threadIdx.x;
    sl[t] = d_loss_partial[t];
    float avg = (float)d_counts[t] * (1.0f / (float)N_ROWS);
    se[t] = avg * logf(avg + 1e-10f);
    __syncthreads();
    for (int s = 512; s; s >>= 1) {
        if (t < s) { sl[t] += sl[t + s]; se[t] += se[t + s]; }
        __syncthreads();
    }
    if (t == 0) {
        const size_t ND = (size_t)N_ROWS * D_DIM;
        out[ND]     = sl[0] / ((float)N_ROWS * (float)D_DIM);
        out[ND + 1] = expf(-se[0]);
    }
}

// ---------------------------------------------------------------------------
extern "C" void kernel_launch(void* const* d_in, const int* in_sizes, int n_in,
                              void* d_out, int out_size) {
    const float* inputs = (const float*)d_in[0];  // [131072, 256]
    const float* embed  = (const float*)d_in[1];  // [256, 1024]
    float* out = (float*)d_out;

    cudaFuncSetAttribute(vq_main_mma,
                         cudaFuncAttributeMaxDynamicSharedMemorySize,
                         SMEM_TOTAL);

    vq_prep<<<8, 128>>>(embed);
    vq_prep_frag<<<64, 256>>>(embed);
    vq_main_mma<<<N_ROWS / 128, 256, SMEM_TOTAL>>>(inputs, out);
    vq_fix<<<256, 256>>>(inputs, out);
    vq_finalize<<<1, 1024>>>(out);
}

// round 13
// speedup vs baseline: 2.4074x; 1.6527x over previous
#include <cuda_runtime.h>
#include <cuda_bf16.h>
#include <cuda_fp16.h>
#include <math.h>
#include <stdint.h>

#define K_CODES 1024
#define D_DIM   256
#define N_ROWS  131072

#define MMA_CTAS     512       // rows 0..65535, 128/CTA
#define FFMA_CTAS    1024      // rows 65536..131071, 64/CTA
#define THRESH_MMA   0.65f     // bf16 f32-acc err std ~0.07
#define THRESH_FFMA  1.0f      // fp16 half2-acc err std ~0.1
#define RESCUE_RPB   8

// ---------------- scratch (device globals; no allocations allowed) ----------
__device__ float        d_cnorm[K_CODES];
__device__ float        d_embedT[K_CODES * D_DIM];
__device__ uint32_t     d_eBfrag[64 * 2048];         // bf16 frags (MMA path)
__device__ uint32_t     d_eBfrag16[64 * 2048];       // fp16 frags (FFMA path)
__device__ unsigned int d_counts[K_CODES];
__device__ float        d_loss_partial[1536];
__device__ int          d_nflag;
__device__ int          d_flaglist[N_ROWS];

__device__ __forceinline__ uint32_t pack_bf2(float a, float b) {
    __nv_bfloat16 ha = __float2bfloat16_rn(a), hb = __float2bfloat16_rn(b);
    return (uint32_t)__bfloat16_as_ushort(ha) |
           ((uint32_t)__bfloat16_as_ushort(hb) << 16);
}
__device__ __forceinline__ uint32_t pack_h2(float a, float b) {
    __half2 h = __floats2half2_rn(a, b);
    return *(uint32_t*)&h;
}

// ---------------------------------------------------------------------------
// Prep 1: emulated codebook norms, fp32 transpose
// ---------------------------------------------------------------------------
__global__ void vq_prep(const float* __restrict__ embed) {
    int k = blockIdx.x * blockDim.x + threadIdx.x;
    float s = 0.0f;
    for (int d = 0; d < D_DIM; ++d) {
        float v = embed[(size_t)d * K_CODES + k];
        s = __fadd_rn(s, __fmul_rn(v, v));
        d_embedT[(size_t)k * D_DIM + d] = v;
    }
    d_cnorm[k]  = s;
    d_counts[k] = 0u;
    if (k == 0) d_nflag = 0;
}

// ---------------------------------------------------------------------------
// Prep 2: B fragments, chunk-linear (bf16 + fp16 twins)
// ---------------------------------------------------------------------------
__global__ void vq_prep_frag(const float* __restrict__ embed) {
    const int g = blockIdx.x;          // 0..63
    const int kc = g >> 3, dc = g & 7;
    #pragma unroll
    for (int q = 0; q < 4; ++q) {
        int e    = q * 256 + threadIdx.x;   // 0..1023
        int ks   = e >> 9;
        int nt   = (e >> 5) & 15;
        int lane = e & 31;
        int t4   = lane & 3;
        int gq   = lane >> 2;
        int code = kc * 128 + nt * 8 + gq;
        int db   = dc * 32 + ks * 16;
        float e0 = embed[(size_t)(db + 2*t4)     * K_CODES + code];
        float e1 = embed[(size_t)(db + 2*t4 + 1) * K_CODES + code];
        float e2 = embed[(size_t)(db + 2*t4 + 8) * K_CODES + code];
        float e3 = embed[(size_t)(db + 2*t4 + 9) * K_CODES + code];
        size_t o = (size_t)g * 2048 + (size_t)e * 2;
        d_eBfrag[o]       = pack_bf2(e0, e1);
        d_eBfrag[o + 1]   = pack_bf2(e2, e3);
        d_eBfrag16[o]     = pack_h2(e0, e1);
        d_eBfrag16[o + 1] = pack_h2(e2, e3);
    }
}

// ---------------------------------------------------------------------------
// SMEM (bytes): [0,4096) sCn | [4096,4608) sIdx | [4608,4640) sRed
// MMA path:  [4640,70176) fragA | [70176,86560) fragB (2x2048 u32)
// FFMA path: [4640,39456) sAh [128][68] h2 | [39456,56352) sBh 2x[16][132] h2
// ---------------------------------------------------------------------------
#define SM_CN   0
#define SM_IDX  4096
#define SM_RED  4608
#define SM_A    4640
#define SM_B    70176
#define SMEM_TOTAL 86560
#define BSTRIDE 2048

__device__ __forceinline__ void mma_bf16(float c[4], uint32_t a0, uint32_t a1,
                                         uint32_t a2, uint32_t a3,
                                         uint32_t b0, uint32_t b1) {
    asm volatile(
        "mma.sync.aligned.m16n8k16.row.col.f32.bf16.bf16.f32 "
        "{%0,%1,%2,%3}, {%4,%5,%6,%7}, {%8,%9}, {%0,%1,%2,%3};"
        : "+f"(c[0]), "+f"(c[1]), "+f"(c[2]), "+f"(c[3])
        : "r"(a0), "r"(a1), "r"(a2), "r"(a3), "r"(b0), "r"(b1));
}

__device__ __forceinline__ void top2_upd(float& v1, float& v2, int& i1,
                                         float d, int code) {
    if (d < v1)      { v2 = v1; v1 = d; i1 = code; }
    else if (d < v2) { v2 = d; }
}

__global__ void __launch_bounds__(256, 2)
vq_main_hybrid(const float* __restrict__ inputs, float* __restrict__ out) {
    extern __shared__ char smem[];
    float* sCn  = (float*)(smem + SM_CN);
    int*   sIdx = (int*)(smem + SM_IDX);
    float* sRed = (float*)(smem + SM_RED);

    const int t    = threadIdx.x;
    const int lane = t & 31;
    const size_t ND = (size_t)N_ROWS * D_DIM;

    for (int i = t; i < K_CODES; i += 256) sCn[i] = d_cnorm[i];

    if (blockIdx.x < MMA_CTAS) {
        // ================= MMA path (identical to R10) =====================
        uint32_t* fragA = (uint32_t*)(smem + SM_A);
        uint32_t* fragB = (uint32_t*)(smem + SM_B);
        const int wid  = t >> 5;
        const int row0 = blockIdx.x * 128;

        {
            const float4* in4 = (const float4*)(inputs + (size_t)row0 * D_DIM);
            #pragma unroll
            for (int i = 0; i < 32; ++i) {
                int l   = i * 256 + t;
                int row = l >> 6;
                int d4  = l & 63;
                float4 v = in4[row * 64 + d4];
                int d   = d4 * 4;
                int mt  = row >> 4, r16 = row & 15;
                int ks16 = d >> 4;
                int o    = d & 15;
                int reg  = ((o & 8) ? 2 : 0) + ((r16 >= 8) ? 1 : 0);
                int t0   = (o & 7) >> 1;
                uint32_t* p = fragA + ((mt * 16 + ks16) * 32 + (r16 & 7) * 4 + t0) * 4 + reg;
                p[0] = pack_bf2(v.x, v.y);
                p[4] = pack_bf2(v.z, v.w);
            }
        }
        uint4 pv0, pv1;
        {
            const uint4* src = (const uint4*)d_eBfrag;
            pv0 = src[t];
            pv1 = src[t + 256];
            uint4* dst = (uint4*)fragB;
            dst[t]       = pv0;
            dst[t + 256] = pv1;
        }
        __syncthreads();

        float acc[16][4];
        #pragma unroll
        for (int nt = 0; nt < 16; ++nt)
            #pragma unroll
            for (int r = 0; r < 4; ++r) acc[nt][r] = 0.0f;

        float v1a = 3.4e38f, v2a = 3.4e38f; int i1a = 0;
        float v1b = 3.4e38f, v2b = 3.4e38f; int i1b = 0;

        const uint32_t* fA = fragA + wid * 2048 + lane * 4;

        for (int g = 0; g < 64; ++g) {
            if (g < 63) {
                const uint4* src = (const uint4*)(d_eBfrag + (size_t)(g + 1) * 2048);
                pv0 = src[t];
                pv1 = src[t + 256];
            }
            {
                const uint32_t* fB = fragB + (g & 1) * BSTRIDE + lane * 2;
                #pragma unroll
                for (int ks = 0; ks < 2; ++ks) {
                    int ks16 = (g & 7) * 2 + ks;
                    uint4 a = *(const uint4*)(fA + ks16 * 128);
                    #pragma unroll
                    for (int nt = 0; nt < 16; ++nt) {
                        uint2 b = *(const uint2*)(fB + (ks * 16 + nt) * 64);
                        mma_bf16(acc[nt], a.x, a.y, a.z, a.w, b.x, b.y);
                    }
                }
            }
            if ((g & 7) == 7) {
                int kc = g >> 3;
                #pragma unroll
                for (int nt = 0; nt < 16; ++nt) {
                    int code = kc * 128 + nt * 8 + (lane & 3) * 2;
                    float c0 = sCn[code]     - 2.0f * acc[nt][0];
                    float c1 = sCn[code + 1] - 2.0f * acc[nt][1];
                    float c2 = sCn[code]     - 2.0f * acc[nt][2];
                    float c3 = sCn[code + 1] - 2.0f * acc[nt][3];
                    top2_upd(v1a, v2a, i1a, c0, code);
                    top2_upd(v1a, v2a, i1a, c1, code + 1);
                    top2_upd(v1b, v2b, i1b, c2, code);
                    top2_upd(v1b, v2b, i1b, c3, code + 1);
                    acc[nt][0] = acc[nt][1] = acc[nt][2] = acc[nt][3] = 0.0f;
                }
            }
            if (g < 63) {
                uint4* dst = (uint4*)(fragB + ((g + 1) & 1) * BSTRIDE);
                dst[t]       = pv0;
                dst[t + 256] = pv1;
            }
            __syncthreads();
        }

        #pragma unroll
        for (int off = 1; off < 4; off <<= 1) {
            float w1 = __shfl_down_sync(0xffffffffu, v1a, off, 4);
            int   wi = __shfl_down_sync(0xffffffffu, i1a, off, 4);
            float w2 = __shfl_down_sync(0xffffffffu, v2a, off, 4);
            if (w1 < v1a || (w1 == v1a && wi < i1a)) {
                v2a = fminf(v1a, w2); v1a = w1; i1a = wi;
            } else v2a = fminf(v2a, w1);
            w1 = __shfl_down_sync(0xffffffffu, v1b, off, 4);
            wi = __shfl_down_sync(0xffffffffu, i1b, off, 4);
            w2 = __shfl_down_sync(0xffffffffu, v2b, off, 4);
            if (w1 < v1b || (w1 == v1b && wi < i1b)) {
                v2b = fminf(v1b, w2); v1b = w1; i1b = wi;
            } else v2b = fminf(v2b, w1);
        }

        if ((lane & 3) == 0) {
            int rA = wid * 16 + (lane >> 2);
            int rB = rA + 8;
            sIdx[rA] = i1a;
            sIdx[rB] = i1b;
            if (v2a - v1a < THRESH_MMA) {
                int pos = atomicAdd(&d_nflag, 1);
                d_flaglist[pos] = row0 + rA;
            }
            if (v2b - v1b < THRESH_MMA) {
                int pos = atomicAdd(&d_nflag, 1);
                d_flaglist[pos] = row0 + rB;
            }
            atomicAdd(&d_counts[i1a], 1u);
            atomicAdd(&d_counts[i1b], 1u);
            out[ND + 2 + (size_t)(row0 + rA)] = (float)i1a;
            out[ND + 2 + (size_t)(row0 + rB)] = (float)i1b;
        }
        __syncthreads();

        float lsum = 0.0f;
        const float4* inp4 = (const float4*)(inputs + (size_t)row0 * D_DIM);
        float4*       out4 = (float4*)(out + (size_t)row0 * D_DIM);
        const float4* eT4  = (const float4*)d_embedT;
        #pragma unroll 4
        for (int it = 0; it < 32; ++it) {
            int l  = it * 256 + t;
            int r  = l >> 6;
            int d4 = l & 63;
            float4 x = inp4[r * 64 + d4];
            int    k = sIdx[r];
            float4 q = eT4[(size_t)k * 64 + d4];
            float dx = q.x - x.x, dy = q.y - x.y, dz = q.z - x.z, dw = q.w - x.w;
            lsum += dx * dx + dy * dy + dz * dz + dw * dw;
            out4[r * 64 + d4] = q;
        }
        #pragma unroll
        for (int off = 16; off; off >>= 1)
            lsum += __shfl_down_sync(0xffffffffu, lsum, off);
        if ((t & 31) == 0) sRed[t >> 5] = lsum;
        __syncthreads();
        if (t == 0) {
            float s = 0.0f;
            #pragma unroll
            for (int w = 0; w < 8; ++w) s += sRed[w];
            d_loss_partial[blockIdx.x] = s;
        }
    } else {
        // ================= HFMA2 SIMT path (fp16, FMA pipe) ================
        uint32_t* sAh = (uint32_t*)(smem + SM_A);            // [128][68] h2
        uint32_t* sBh = (uint32_t*)(smem + SM_A + 34816);    // [2][16*132] h2
        const int tx = t & 15, ty = t >> 4;
        const int row0 = MMA_CTAS * 128 + (blockIdx.x - MMA_CTAS) * 64;

        const float4* inp4 = (const float4*)(inputs + (size_t)row0 * D_DIM);
        // Stage A: fp16 half2, transposed [d2][row], pad 68
        #pragma unroll
        for (int it = 0; it < 16; ++it) {
            int l  = it * 256 + t;
            int r  = l >> 6;          // 0..63
            int d4 = l & 63;
            float4 v = inp4[r * 64 + d4];
            sAh[(2 * d4) * 68 + r]     = pack_h2(v.x, v.y);
            sAh[(2 * d4 + 1) * 68 + r] = pack_h2(v.z, v.w);
        }
        // Stage B chunk 0
        uint32_t bw[8];
        #pragma unroll
        for (int q = 0; q < 8; ++q) bw[q] = d_eBfrag16[q * 256 + t];
        #pragma unroll
        for (int q = 0; q < 8; ++q) {
            int idx = q * 256 + t;
            int p_ = idx >> 1, hw = idx & 1;
            int d2 = (p_ >> 9) * 8 + hw * 4 + (p_ & 3);
            int c  = (((p_ >> 5) & 15) << 3) + ((p_ & 31) >> 2);
            sBh[d2 * 132 + c] = bw[q];
        }
        __syncthreads();

        __half2 accp[4][8];
        const __half2 hz = __floats2half2_rn(0.0f, 0.0f);
        #pragma unroll
        for (int r = 0; r < 4; ++r)
            #pragma unroll
            for (int c = 0; c < 8; ++c) accp[r][c] = hz;

        float v1[4], v2[4]; int i1[4];
        #pragma unroll
        for (int r = 0; r < 4; ++r) { v1[r] = 3.4e38f; v2[r] = 3.4e38f; i1[r] = 0; }

        for (int g = 0; g < 64; ++g) {
            if (g < 63) {
                const uint32_t* src = d_eBfrag16 + (size_t)(g + 1) * 2048;
                #pragma unroll
                for (int q = 0; q < 8; ++q) bw[q] = src[q * 256 + t];
            }
            {
                const uint32_t* bb = sBh + (g & 1) * 2112;
                const int dbase = (g & 7) * 16;
                #pragma unroll
                for (int l2 = 0; l2 < 16; ++l2) {
                    uint4 au = *(const uint4*)(sAh + (dbase + l2) * 68 + ty * 4);
                    uint4 b0 = *(const uint4*)(bb + l2 * 132 + tx * 8);
                    uint4 b1 = *(const uint4*)(bb + l2 * 132 + tx * 8 + 4);
                    __half2 ar[4] = {*(__half2*)&au.x, *(__half2*)&au.y,
                                     *(__half2*)&au.z, *(__half2*)&au.w};
                    __half2 bc[8] = {*(__half2*)&b0.x, *(__half2*)&b0.y,
                                     *(__half2*)&b0.z, *(__half2*)&b0.w,
                                     *(__half2*)&b1.x, *(__half2*)&b1.y,
                                     *(__half2*)&b1.z, *(__half2*)&b1.w};
                    #pragma unroll
                    for (int r = 0; r < 4; ++r)
                        #pragma unroll
                        for (int c = 0; c < 8; ++c)
                            accp[r][c] = __hfma2(ar[r], bc[c], accp[r][c]);
                }
            }
            if ((g & 7) == 7) {
                int codebase = (g >> 3) * 128 + tx * 8;
                #pragma unroll
                for (int r = 0; r < 4; ++r)
                    #pragma unroll
                    for (int c = 0; c < 8; ++c) {
                        float f = __low2float(accp[r][c]) + __high2float(accp[r][c]);
                        float dist = sCn[codebase + c] - 2.0f * f;
                        top2_upd(v1[r], v2[r], i1[r], dist, codebase + c);
                        accp[r][c] = hz;
                    }
            }
            if (g < 63) {
                uint32_t* dst = sBh + ((g + 1) & 1) * 2112;
                #pragma unroll
                for (int q = 0; q < 8; ++q) {
                    int idx = q * 256 + t;
                    int p_ = idx >> 1, hw = idx & 1;
                    int d2 = (p_ >> 9) * 8 + hw * 4 + (p_ & 3);
                    int c  = (((p_ >> 5) & 15) << 3) + ((p_ & 31) >> 2);
                    dst[d2 * 132 + c] = bw[q];
                }
            }
            __syncthreads();
        }

        // merge top-2 across the 16 tx lanes sharing each row
        #pragma unroll
        for (int off = 1; off < 16; off <<= 1) {
            #pragma unroll
            for (int r = 0; r < 4; ++r) {
                float w1 = __shfl_down_sync(0xffffffffu, v1[r], off, 16);
                int   wi = __shfl_down_sync(0xffffffffu, i1[r], off, 16);
                float w2 = __shfl_down_sync(0xffffffffu, v2[r], off, 16);
                if (w1 < v1[r] || (w1 == v1[r] && wi < i1[r])) {
                    v2[r] = fminf(v1[r], w2); v1[r] = w1; i1[r] = wi;
                } else v2[r] = fminf(v2[r], w1);
            }
        }
        if (tx == 0) {
            #pragma unroll
            for (int r = 0; r < 4; ++r) {
                int rl = ty * 4 + r;
                sIdx[rl] = i1[r];
                if (v2[r] - v1[r] < THRESH_FFMA) {
                    int pos = atomicAdd(&d_nflag, 1);
                    d_flaglist[pos] = row0 + rl;
                }
                atomicAdd(&d_counts[i1[r]], 1u);
                out[ND + 2 + (size_t)(row0 + rl)] = (float)i1[r];
            }
        }
        __syncthreads();

        float lsum = 0.0f;
        float4*       out4 = (float4*)(out + (size_t)row0 * D_DIM);
        const float4* eT4  = (const float4*)d_embedT;
        #pragma unroll 4
        for (int it = 0; it < 16; ++it) {
            int l  = it * 256 + t;
            int r  = l >> 6;
            int d4 = l & 63;
            float4 x = inp4[r * 64 + d4];
            int    k = sIdx[r];
            float4 q = eT4[(size_t)k * 64 + d4];
            float dx = q.x - x.x, dy = q.y - x.y, dz = q.z - x.z, dw = q.w - x.w;
            lsum += dx * dx + dy * dy + dz * dz + dw * dw;
            out4[r * 64 + d4] = q;
        }
        #pragma unroll
        for (int off = 16; off; off >>= 1)
            lsum += __shfl_down_sync(0xffffffffu, lsum, off);
        if ((t & 31) == 0) sRed[t >> 5] = lsum;
        __syncthreads();
        if (t == 0) {
            float s = 0.0f;
            #pragma unroll
            for (int w = 0; w < 8; ++w) s += sRed[w];
            d_loss_partial[blockIdx.x] = s;
        }
    }
}

// ---------------------------------------------------------------------------
// Rescue: re-decide flagged rows with reference-emulated fp32 arithmetic
// ---------------------------------------------------------------------------
__global__ void __launch_bounds__(256)
vq_fix(const float* __restrict__ inputs, float* __restrict__ out) {
    __shared__ float sx[RESCUE_RPB][D_DIM];
    __shared__ float sdist[RESCUE_RPB][K_CODES];
    __shared__ float ssx2[RESCUE_RPB];
    __shared__ int   srow[RESCUE_RPB];
    __shared__ int   sbest[RESCUE_RPB];
    const int t = threadIdx.x;
    const size_t ND = (size_t)N_ROWS * D_DIM;

    const int nf = d_nflag;
    for (int base = blockIdx.x * RESCUE_RPB; base < nf;
         base += gridDim.x * RESCUE_RPB) {
        const int cnt = min(RESCUE_RPB, nf - base);
        __syncthreads();
        if (t < cnt) srow[t] = d_flaglist[base + t];
        __syncthreads();
        for (int r = 0; r < cnt; ++r)
            sx[r][t] = inputs[(size_t)srow[r] * D_DIM + t];
        __syncthreads();
        if (t < cnt) {
            float s = 0.0f;
            for (int d = 0; d < D_DIM; ++d)
                s = __fadd_rn(s, __fmul_rn(sx[t][d], sx[t][d]));
            ssx2[t] = s;
        }
        __syncthreads();

        #pragma unroll
        for (int c = 0; c < 4; ++c) {
            const int k = c * 256 + t;
            const float* e = d_embedT + (size_t)k * D_DIM;
            float acc[RESCUE_RPB];
            #pragma unroll
            for (int r = 0; r < RESCUE_RPB; ++r) acc[r] = 0.0f;
            for (int d = 0; d < D_DIM; ++d) {
                float ev = e[d];
                #pragma unroll
                for (int r = 0; r < RESCUE_RPB; ++r)
                    acc[r] = __fmaf_rn(sx[r][d], ev, acc[r]);
            }
            #pragma unroll
            for (int r = 0; r < RESCUE_RPB; ++r) {
                float twod = __fadd_rn(acc[r], acc[r]);
                float t1   = __fsub_rn(ssx2[r], twod);
                sdist[r][k] = __fadd_rn(t1, d_cnorm[k]);
            }
        }
        __syncthreads();

        if (t < cnt) {
            float best = 3.4e38f; int bk = 0;
            for (int k = 0; k < K_CODES; ++k) {
                float v = sdist[t][k];
                if (v < best) { best = v; bk = k; }
            }
            sbest[t] = bk;
            int oldk = (int)out[ND + 2 + (size_t)srow[t]];
            if (oldk != bk) {
                atomicAdd(&d_counts[bk], 1u);
                atomicAdd(&d_counts[oldk], 0xFFFFFFFFu);
                out[ND + 2 + (size_t)srow[t]] = (float)bk;
            }
        }
        __syncthreads();
        for (int r = 0; r < cnt; ++r)
            out[(size_t)srow[r] * D_DIM + t] =
                d_embedT[(size_t)sbest[r] * D_DIM + t];
    }
}

// ---------------------------------------------------------------------------
// Finalize: loss mean + perplexity (1536 partials)
// ---------------------------------------------------------------------------
__global__ void vq_finalize(float* __restrict__ out) {
    __shared__ float sl[1024];
    __shared__ float se[1024];
    int t = threadIdx.x;
    float p = d_loss_partial[t];
    if (t < 512) p += d_loss_partial[1024 + t];
    sl[t] = p;
    float avg = (float)d_counts[t] * (1.0f / (float)N_ROWS);
    se[t] = avg * logf(avg + 1e-10f);
    __syncthreads();
    for (int s = 512; s; s >>= 1) {
        if (t < s) { sl[t] += sl[t + s]; se[t] += se[t + s]; }
        __syncthreads();
    }
    if (t == 0) {
        const size_t ND = (size_t)N_ROWS * D_DIM;
        out[ND]     = sl[0] / ((float)N_ROWS * (float)D_DIM);
        out[ND + 1] = expf(-se[0]);
    }
}

// ---------------------------------------------------------------------------
extern "C" void kernel_launch(void* const* d_in, const int* in_sizes, int n_in,
                              void* d_out, int out_size) {
    const float* inputs = (const float*)d_in[0];  // [131072, 256]
    const float* embed  = (const float*)d_in[1];  // [256, 1024]
    float* out = (float*)d_out;

    cudaFuncSetAttribute(vq_main_hybrid,
                         cudaFuncAttributeMaxDynamicSharedMemorySize,
                         SMEM_TOTAL);

    vq_prep<<<8, 128>>>(embed);
    vq_prep_frag<<<64, 256>>>(embed);
    vq_main_hybrid<<<MMA_CTAS + FFMA_CTAS, 256, SMEM_TOTAL>>>(inputs, out);
    vq_fix<<<256, 256>>>(inputs, out);
    vq_finalize<<<1, 1024>>>(out);
}